// round 10
// baseline (speedup 1.0000x reference)
#include <cuda_runtime.h>
#include <cstdint>

typedef unsigned int u32;

static constexpr int D = 1024;
static constexpr int K = 32;
static constexpr int NT = 512;        // 16 warps
static constexpr int TILE_R = 32;     // rows per block (H tile resident in smem)
static constexpr int DC = 64;         // d per chunk
static constexpr int NCH = D / DC;    // 16

static constexpr int HSTR = 1028;     // H tile row stride (== 4 mod 32)
// smem float offsets
static constexpr int OFF_HS = 0;                    // 32*1028 = 32896
static constexpr int OFF_VS = 32896;                // 3 * 32*68 = 6528
static constexpr int VSB    = 2176;                 // 32*68 per buffer
static constexpr int OFF_W  = 39424;                // 32*36 = 1152
static constexpr int OFF_CR = 40576;                // 2 slabs: Pt2 2*1056 / corr2 2*2176
static constexpr int CRB    = 2176;
static constexpr int OFF_SC = 44928;                // 1024
static constexpr int SM_FLOATS = 45952;             // 183,808 bytes

__device__ float g_G[K * K];
__device__ float g_C[K * K];

__device__ __forceinline__ u32 tf32r(float x) {
    u32 r;
    asm("cvt.rna.tf32.f32 %0, %1;" : "=r"(r) : "f"(x));
    return r;
}
__device__ __forceinline__ void mma8(float* d, u32 a0, u32 a1, u32 a2, u32 a3,
                                     u32 b0, u32 b1) {
    asm volatile("mma.sync.aligned.m16n8k8.row.col.f32.tf32.tf32.f32 "
        "{%0,%1,%2,%3}, {%4,%5,%6,%7}, {%8,%9}, {%0,%1,%2,%3};"
        : "+f"(d[0]), "+f"(d[1]), "+f"(d[2]), "+f"(d[3])
        : "r"(a0), "r"(a1), "r"(a2), "r"(a3), "r"(b0), "r"(b1));
}
__device__ __forceinline__ void cp16(float* s, const float* g) {
    u32 ss = (u32)__cvta_generic_to_shared(s);
    asm volatile("cp.async.cg.shared.global [%0], [%1], 16;" :: "r"(ss), "l"(g) : "memory");
}
#define CP_COMMIT() asm volatile("cp.async.commit_group;" ::: "memory")
#define CP_WAIT2()  asm volatile("cp.async.wait_group 2;" ::: "memory")
#define CP_WAIT1()  asm volatile("cp.async.wait_group 1;" ::: "memory")
#define CP_WAIT0()  asm volatile("cp.async.wait_group 0;" ::: "memory")

// ---------------- G = V V^T ----------------
__global__ void gram_kernel(const float* __restrict__ V) {
    int k1 = blockIdx.x;
    int w = threadIdx.x >> 5;
    int lane = threadIdx.x & 31;
    #pragma unroll
    for (int i = 0; i < 4; i++) {
        int k2 = w * 4 + i;
        float s = 0.f;
        #pragma unroll
        for (int j = 0; j < D; j += 128) {
            float4 a = *(const float4*)(V + k1 * D + j + lane * 4);
            float4 b = *(const float4*)(V + k2 * D + j + lane * 4);
            s += a.x * b.x + a.y * b.y + a.z * b.z + a.w * b.w;
        }
        #pragma unroll
        for (int o = 16; o; o >>= 1) s += __shfl_down_sync(0xffffffffu, s, o);
        if (lane == 0) g_G[k1 * K + k2] = s;
    }
}

// ---------------- C = (I+U)^{-1} diag(beta) ----------------
__global__ void prepc_kernel() {
    __shared__ float G[K * K];
    __shared__ float beta[K];
    int t = threadIdx.x;
    for (int i = t; i < K * K; i += 32) G[i] = g_G[i];
    __syncwarp();
    beta[t] = 1.f / G[t * K + t];
    __syncwarp();
    float x[K];
    int c = t;
    for (int j = 0; j < K; j++) x[j] = 0.f;
    x[c] = 1.f;
    for (int j = c - 1; j >= 0; j--) {
        float s = 0.f;
        for (int m = j + 1; m <= c; m++) s += beta[j] * G[j * K + m] * x[m];
        x[j] = -s;
    }
    for (int j = 0; j < K; j++) g_C[j * K + c] = x[j] * beta[c];
}

// ---------------- fused single-pass: out = h - ((h V^T) C) V ----------------
__global__ __launch_bounds__(NT, 1) void fused_kernel(
    const float* __restrict__ H, const float* __restrict__ V,
    float* __restrict__ OUT)
{
    extern __shared__ __align__(16) float sm[];

    const int t = threadIdx.x;
    const int wid = t >> 5;
    const int lid = t & 31;
    const int g = lid >> 2;          // frag group 0..7
    const int tq = lid & 3;          // frag thread 0..3
    const int wr = wid & 1;          // m half (16)
    const int wn = (wid >> 1) & 3;   // n tile (8)
    const int wd = wid >> 3;         // contraction split half
    const int row0 = blockIdx.x * TILE_R;

    float* sC = sm + OFF_SC;
    for (int i = t; i < K * K; i += NT) sC[i] = g_C[i];

    const int sr = t >> 4;           // staging row 0..31
    const int sc16 = t & 15;         // staging float4 col 0..15

    auto stageH = [&](int c) {       // H chunk 32x64 -> resident Hs
        cp16(sm + OFF_HS + sr * HSTR + c * DC + sc16 * 4,
             H + (size_t)(row0 + sr) * D + c * DC + sc16 * 4);
    };
    auto stageV = [&](int c, int b) {// V chunk 32(k)x64(d), stride 68
        cp16(sm + OFF_VS + b * VSB + sr * 68 + sc16 * 4,
             V + (size_t)sr * D + c * DC + sc16 * 4);
    };

    // ============ Phase A: Pt = V H^T (contraction over d) ============
    float pacc[4] = {0.f, 0.f, 0.f, 0.f};

    stageH(0); stageV(0, 0); CP_COMMIT();
    stageH(1); stageV(1, 1); CP_COMMIT();
    for (int c = 0; c < NCH; c++) {
        if (c + 2 < NCH) { stageH(c + 2); stageV(c + 2, (c + 2) % 3); CP_COMMIT(); CP_WAIT2(); }
        else if (c + 1 < NCH) CP_WAIT1();
        else CP_WAIT0();
        __syncthreads();
        const float* vs = sm + OFF_VS + (c % 3) * VSB;
        const float* hs = sm + OFF_HS;
        const int dcg = c * DC;
        #pragma unroll
        for (int ks = 0; ks < 4; ks++) {
            int d0 = (wd * 4 + ks) * 8;
            u32 a0 = tf32r(vs[(wr * 16 + g) * 68 + d0 + tq]);
            u32 a1 = tf32r(vs[(wr * 16 + g + 8) * 68 + d0 + tq]);
            u32 a2 = tf32r(vs[(wr * 16 + g) * 68 + d0 + tq + 4]);
            u32 a3 = tf32r(vs[(wr * 16 + g + 8) * 68 + d0 + tq + 4]);
            u32 b0 = tf32r(hs[(wn * 8 + g) * HSTR + dcg + d0 + tq]);
            u32 b1 = tf32r(hs[(wn * 8 + g) * HSTR + dcg + d0 + tq + 4]);
            mma8(pacc, a0, a1, a2, a3, b0, b1);
        }
        __syncthreads();
    }

    // write Pt partials: Pt2[wd][kidx][hrow], stride 33
    {
        float* Pt = sm + OFF_CR + wd * 1056;
        int col = wn * 8 + 2 * tq;
        Pt[(wr * 16 + g) * 33 + col] = pacc[0];
        Pt[(wr * 16 + g) * 33 + col + 1] = pacc[1];
        Pt[(wr * 16 + g + 8) * 33 + col] = pacc[2];
        Pt[(wr * 16 + g + 8) * 33 + col + 1] = pacc[3];
    }
    __syncthreads();

    // prefetch phase-B V chunks 0,1 (buffers free: last A chunk used buf 0; reads done)
    stageV(0, 0); CP_COMMIT();
    stageV(1, 1); CP_COMMIT();

    // W = P C on CUDA cores: W[hrow][c] = sum_j (Pt0+Pt1)[j][hrow] * C[j][c]
    if (t < 256) {
        const float* Pa = sm + OFF_CR;
        const float* Pb = Pa + 1056;
        float* W = sm + OFF_W;
        int r = t >> 3, cq = t & 7;
        float4 wv = {0.f, 0.f, 0.f, 0.f};
        #pragma unroll 4
        for (int j = 0; j < K; j++) {
            float pj = Pa[j * 33 + r] + Pb[j * 33 + r];
            float4 cv = *(const float4*)(&sC[j * K + cq * 4]);
            wv.x += pj * cv.x; wv.y += pj * cv.y;
            wv.z += pj * cv.z; wv.w += pj * cv.w;
        }
        *(float4*)(&W[r * 36 + cq * 4]) = wv;
    }
    __syncthreads();

    // hoist W a-fragments for this warp's k-half (constant over all B chunks)
    u32 wa[2][4];
    {
        const float* W = sm + OFF_W;
        #pragma unroll
        for (int ks = 0; ks < 2; ks++) {
            int k0 = wd * 16 + ks * 8;
            wa[ks][0] = tf32r(W[(wr * 16 + g) * 36 + k0 + tq]);
            wa[ks][1] = tf32r(W[(wr * 16 + g + 8) * 36 + k0 + tq]);
            wa[ks][2] = tf32r(W[(wr * 16 + g) * 36 + k0 + tq + 4]);
            wa[ks][3] = tf32r(W[(wr * 16 + g + 8) * 36 + k0 + tq + 4]);
        }
    }

    // ============ Phase B: corr = W V; out = h_smem - corr ============
    float* cr = sm + OFF_CR;         // corr2: 2 slabs stride 68 (Pt dead)
    for (int c = 0; c < NCH; c++) {
        if (c + 2 < NCH) { stageV(c + 2, (c + 2) % 3); CP_COMMIT(); CP_WAIT2(); }
        else if (c + 1 < NCH) CP_WAIT1();
        else CP_WAIT0();
        __syncthreads();
        const float* vs = sm + OFF_VS + (c % 3) * VSB;
        float* crw = cr + wd * CRB;
        #pragma unroll
        for (int nt = 0; nt < 2; nt++) {
            float acc[4] = {0.f, 0.f, 0.f, 0.f};
            #pragma unroll
            for (int ks = 0; ks < 2; ks++) {
                int k0 = wd * 16 + ks * 8;
                u32 b0 = tf32r(vs[(k0 + tq) * 68 + nt * 32 + wn * 8 + g]);
                u32 b1 = tf32r(vs[(k0 + tq + 4) * 68 + nt * 32 + wn * 8 + g]);
                mma8(acc, wa[ks][0], wa[ks][1], wa[ks][2], wa[ks][3], b0, b1);
            }
            int col = nt * 32 + wn * 8 + 2 * tq;
            crw[(wr * 16 + g) * 68 + col] = acc[0];
            crw[(wr * 16 + g) * 68 + col + 1] = acc[1];
            crw[(wr * 16 + g + 8) * 68 + col] = acc[2];
            crw[(wr * 16 + g + 8) * 68 + col + 1] = acc[3];
        }
        __syncthreads();
        // epilogue: fully coalesced, H from resident smem
        float4 hv = *(const float4*)(&sm[OFF_HS + sr * HSTR + c * DC + sc16 * 4]);
        float4 c0 = *(const float4*)(&cr[sr * 68 + sc16 * 4]);
        float4 c1 = *(const float4*)(&cr[CRB + sr * 68 + sc16 * 4]);
        float4 o = {hv.x - c0.x - c1.x, hv.y - c0.y - c1.y,
                    hv.z - c0.z - c1.z, hv.w - c0.w - c1.w};
        *(float4*)(OUT + (size_t)(row0 + sr) * D + c * DC + sc16 * 4) = o;
    }
}

extern "C" void kernel_launch(void* const* d_in, const int* in_sizes, int n_in,
                              void* d_out, int out_size) {
    const float* H = (const float*)d_in[0];
    const float* V = (const float*)d_in[1];
    float* OUT = (float*)d_out;
    const int N = in_sizes[0] / D;

    cudaFuncSetAttribute(fused_kernel, cudaFuncAttributeMaxDynamicSharedMemorySize,
                         SM_FLOATS * 4);
    gram_kernel<<<K, 256>>>(V);
    prepc_kernel<<<1, 32>>>();
    fused_kernel<<<N / TILE_R, NT, SM_FLOATS * 4>>>(H, V, OUT);
}

// round 11
// speedup vs baseline: 1.4420x; 1.4420x over previous
#include <cuda_runtime.h>
#include <cstdint>

typedef unsigned int u32;

static constexpr int D = 1024;
static constexpr int K = 32;
static constexpr int NT = 256;       // 8 warps
static constexpr int TILE_R = 128;   // rows per block
static constexpr int DC = 32;        // d per chunk
static constexpr int NCH = D / DC;   // 32

// smem float offsets
static constexpr int HS0 = 0;        // 128*36 (H buf 0)
static constexpr int HS1 = 4608;     // 128*36 (H buf 1; also W between phases)
static constexpr int VB0 = 9216;     // 32*40  (V buf 0)
static constexpr int VB1 = 10496;    // 32*40  (V buf 1)
static constexpr int CRO = 11776;    // 128*36 (corr; also P stride-33 at transition)
static constexpr int SCO = 16384;    // 32*32  (C)
static constexpr int SM_FLOATS = 17408;   // 69632 bytes

__device__ float g_G[K * K];
__device__ float g_C[K * K];
__device__ float g_Vt[D * K];        // Vt[d][k]

__device__ __forceinline__ u32 tf32r(float x) {
    u32 r;
    asm("cvt.rna.tf32.f32 %0, %1;" : "=r"(r) : "f"(x));
    return r;
}
__device__ __forceinline__ void mma8(float* d, u32 a0, u32 a1, u32 a2, u32 a3,
                                     u32 b0, u32 b1) {
    asm volatile("mma.sync.aligned.m16n8k8.row.col.f32.tf32.tf32.f32 "
        "{%0,%1,%2,%3}, {%4,%5,%6,%7}, {%8,%9}, {%0,%1,%2,%3};"
        : "+f"(d[0]), "+f"(d[1]), "+f"(d[2]), "+f"(d[3])
        : "r"(a0), "r"(a1), "r"(a2), "r"(a3), "r"(b0), "r"(b1));
}
__device__ __forceinline__ void cp16(float* s, const float* g) {
    u32 ss = (u32)__cvta_generic_to_shared(s);
    asm volatile("cp.async.cg.shared.global [%0], [%1], 16;" :: "r"(ss), "l"(g) : "memory");
}
#define CP_COMMIT() asm volatile("cp.async.commit_group;" ::: "memory")
#define CP_WAIT1()  asm volatile("cp.async.wait_group 1;" ::: "memory")
#define CP_WAIT0()  asm volatile("cp.async.wait_group 0;" ::: "memory")

// ---------------- G = V V^T + build g_Vt ----------------
__global__ void gram_kernel(const float* __restrict__ V) {
    int k1 = blockIdx.x;
    int w = threadIdx.x >> 5;
    int lane = threadIdx.x & 31;
    #pragma unroll
    for (int i = 0; i < 4; i++) {
        int k2 = w * 4 + i;
        float s = 0.f;
        #pragma unroll
        for (int j = 0; j < D; j += 128) {
            float4 a = *(const float4*)(V + k1 * D + j + lane * 4);
            float4 b = *(const float4*)(V + k2 * D + j + lane * 4);
            s += a.x * b.x + a.y * b.y + a.z * b.z + a.w * b.w;
        }
        #pragma unroll
        for (int o = 16; o; o >>= 1) s += __shfl_down_sync(0xffffffffu, s, o);
        if (lane == 0) g_G[k1 * K + k2] = s;
    }
    for (int d = threadIdx.x; d < D; d += 256)
        g_Vt[d * K + k1] = V[k1 * D + d];
}

// ---------------- C = (I+U)^{-1} diag(beta) ----------------
__global__ void prepc_kernel() {
    __shared__ float G[K * K];
    __shared__ float beta[K];
    int t = threadIdx.x;
    for (int i = t; i < K * K; i += 32) G[i] = g_G[i];
    __syncwarp();
    beta[t] = 1.f / G[t * K + t];
    __syncwarp();
    float x[K];
    int c = t;
    for (int j = 0; j < K; j++) x[j] = 0.f;
    x[c] = 1.f;
    for (int j = c - 1; j >= 0; j--) {
        float s = 0.f;
        for (int m = j + 1; m <= c; m++) s += beta[j] * G[j * K + m] * x[m];
        x[j] = -s;
    }
    for (int j = 0; j < K; j++) g_C[j * K + c] = x[j] * beta[c];
}

// ---------------- fused: out = h - ((h V^T) C) V, tf32 mma.sync ----------------
__global__ __launch_bounds__(NT) void fused_kernel(
    const float* __restrict__ H, const float* __restrict__ V,
    float* __restrict__ OUT)
{
    extern __shared__ __align__(16) float sm[];

    const int t = threadIdx.x;
    const int wid = t >> 5;
    const int lid = t & 31;
    const int g = lid >> 2;          // frag group 0..7
    const int tq = lid & 3;          // frag thread 0..3
    const int w16 = wid * 16;        // warp row base
    const int row0 = blockIdx.x * TILE_R;

    float* sC = sm + SCO;
    for (int i = t; i < K * K; i += NT) sC[i] = g_C[i];

    const int fc = t & 7;            // staging float4 col
    const int sr = t >> 3;           // staging row (0..31)

    auto stageH = [&](int c, int b) {      // H tile 128x32, stride 36
        float* dst = sm + (b ? HS1 : HS0);
        int dc = c * DC;
        #pragma unroll
        for (int i = 0; i < 4; i++) {
            int seg = i * 256 + t, r = seg >> 3, c16 = seg & 7;
            cp16(dst + r * 36 + c16 * 4, H + (size_t)(row0 + r) * D + dc + c16 * 4);
        }
    };
    auto stageVt = [&](int c, int b) {     // Vt 32(d)x32(k), stride 40
        float* dst = sm + (b ? VB1 : VB0);
        cp16(dst + sr * 40 + fc * 4, g_Vt + (size_t)(c * DC + sr) * K + fc * 4);
    };
    auto stageVs = [&](int c, int b) {     // Vs 32(k)x32(d), stride 40
        float* dst = sm + (b ? VB1 : VB0);
        cp16(dst + sr * 40 + fc * 4, V + (size_t)sr * D + c * DC + fc * 4);
    };

    // ============ Phase A: P = H V^T ============
    float pacc[4][4];
    #pragma unroll
    for (int nt = 0; nt < 4; nt++)
        #pragma unroll
        for (int i = 0; i < 4; i++) pacc[nt][i] = 0.f;

    stageH(0, 0); stageVt(0, 0); CP_COMMIT();
    for (int c = 0; c < NCH; c++) {
        int b = c & 1;
        if (c + 1 < NCH) {
            stageH(c + 1, b ^ 1); stageVt(c + 1, b ^ 1);
            CP_COMMIT(); CP_WAIT1();
        } else CP_WAIT0();
        __syncthreads();
        const float* hs = sm + (b ? HS1 : HS0);
        const float* vt = sm + (b ? VB1 : VB0);
        #pragma unroll
        for (int ks = 0; ks < 4; ks++) {
            int d0 = ks * 8;
            u32 a0 = tf32r(hs[(w16 + g) * 36 + d0 + tq]);
            u32 a1 = tf32r(hs[(w16 + g + 8) * 36 + d0 + tq]);
            u32 a2 = tf32r(hs[(w16 + g) * 36 + d0 + tq + 4]);
            u32 a3 = tf32r(hs[(w16 + g + 8) * 36 + d0 + tq + 4]);
            #pragma unroll
            for (int nt = 0; nt < 4; nt++) {
                u32 b0 = tf32r(vt[(d0 + tq) * 40 + nt * 8 + g]);
                u32 b1 = tf32r(vt[(d0 + tq + 4) * 40 + nt * 8 + g]);
                mma8(pacc[nt], a0, a1, a2, a3, b0, b1);
            }
        }
        __syncthreads();
    }

    // ---- P -> CR region (stride 33) ----
    {
        float* P = sm + CRO;
        #pragma unroll
        for (int nt = 0; nt < 4; nt++) {
            int cc = nt * 8 + 2 * tq;
            P[(w16 + g) * 33 + cc] = pacc[nt][0];
            P[(w16 + g) * 33 + cc + 1] = pacc[nt][1];
            P[(w16 + g + 8) * 33 + cc] = pacc[nt][2];
            P[(w16 + g + 8) * 33 + cc + 1] = pacc[nt][3];
        }
    }
    // prefetch phase-B chunk 0 (HS0/VB0 free; overlaps W compute)
    stageH(0, 0); stageVs(0, 0); CP_COMMIT();
    __syncthreads();

    // ---- W = P C into HS1 (stride 36) ----
    {
        const float* P = sm + CRO;
        float* W = sm + HS1;
        int r = t & 127, half = t >> 7;
        float wv[16];
        #pragma unroll
        for (int i = 0; i < 16; i++) wv[i] = 0.f;
        #pragma unroll 4
        for (int j = 0; j < K; j++) {
            float pj = P[r * 33 + j];
            #pragma unroll
            for (int c4 = 0; c4 < 4; c4++) {
                float4 cv = *(const float4*)(&sC[j * K + half * 16 + c4 * 4]);
                wv[c4 * 4 + 0] += pj * cv.x;
                wv[c4 * 4 + 1] += pj * cv.y;
                wv[c4 * 4 + 2] += pj * cv.z;
                wv[c4 * 4 + 3] += pj * cv.w;
            }
        }
        #pragma unroll
        for (int i = 0; i < 16; i++) W[r * 36 + half * 16 + i] = wv[i];
    }
    __syncthreads();

    // hoist W a-fragments (then HS1 becomes a pipeline buffer again)
    u32 wa[4][4];
    {
        const float* W = sm + HS1;
        #pragma unroll
        for (int ks = 0; ks < 4; ks++) {
            int k0 = ks * 8;
            wa[ks][0] = tf32r(W[(w16 + g) * 36 + k0 + tq]);
            wa[ks][1] = tf32r(W[(w16 + g + 8) * 36 + k0 + tq]);
            wa[ks][2] = tf32r(W[(w16 + g) * 36 + k0 + tq + 4]);
            wa[ks][3] = tf32r(W[(w16 + g + 8) * 36 + k0 + tq + 4]);
        }
    }
    __syncthreads();

    // ============ Phase B: corr = W V; out = Hs - corr ============
    float* CR = sm + CRO;
    for (int c = 0; c < NCH; c++) {
        int b = c & 1;
        if (c + 1 < NCH) {
            stageH(c + 1, b ^ 1); stageVs(c + 1, b ^ 1);
            CP_COMMIT(); CP_WAIT1();
        } else CP_WAIT0();
        __syncthreads();
        const float* vs = sm + (b ? VB1 : VB0);
        #pragma unroll
        for (int nt = 0; nt < 4; nt++) {
            float acc[4] = {0.f, 0.f, 0.f, 0.f};
            #pragma unroll
            for (int ks = 0; ks < 4; ks++) {
                int k0 = ks * 8;
                u32 b0 = tf32r(vs[(k0 + tq) * 40 + nt * 8 + g]);
                u32 b1 = tf32r(vs[(k0 + tq + 4) * 40 + nt * 8 + g]);
                mma8(acc, wa[ks][0], wa[ks][1], wa[ks][2], wa[ks][3], b0, b1);
            }
            int cc = nt * 8 + 2 * tq;
            CR[(w16 + g) * 36 + cc] = acc[0];
            CR[(w16 + g) * 36 + cc + 1] = acc[1];
            CR[(w16 + g + 8) * 36 + cc] = acc[2];
            CR[(w16 + g + 8) * 36 + cc + 1] = acc[3];
        }
        __syncthreads();
        // coalesced epilogue from smem
        const float* hsb = sm + (b ? HS1 : HS0);
        #pragma unroll
        for (int i = 0; i < 4; i++) {
            int r = i * 32 + sr;
            float4 hv = *(const float4*)(&hsb[r * 36 + fc * 4]);
            float4 cv = *(const float4*)(&CR[r * 36 + fc * 4]);
            float4 o = {hv.x - cv.x, hv.y - cv.y, hv.z - cv.z, hv.w - cv.w};
            *(float4*)(OUT + (size_t)(row0 + r) * D + c * DC + fc * 4) = o;
        }
        __syncthreads();
    }
}

extern "C" void kernel_launch(void* const* d_in, const int* in_sizes, int n_in,
                              void* d_out, int out_size) {
    const float* H = (const float*)d_in[0];
    const float* V = (const float*)d_in[1];
    float* OUT = (float*)d_out;
    const int N = in_sizes[0] / D;

    cudaFuncSetAttribute(fused_kernel, cudaFuncAttributeMaxDynamicSharedMemorySize,
                         SM_FLOATS * 4);
    gram_kernel<<<K, 256>>>(V);
    prepc_kernel<<<1, 32>>>();
    fused_kernel<<<N / TILE_R, NT, SM_FLOATS * 4>>>(H, V, OUT);
}

// round 12
// speedup vs baseline: 1.5587x; 1.0809x over previous
#include <cuda_runtime.h>
#include <cstdint>

typedef unsigned int u32;

static constexpr int D = 1024;
static constexpr int K = 32;
static constexpr int NT = 256;       // 8 warps
static constexpr int TILE_R = 128;   // rows per block
static constexpr int DC = 32;        // d per chunk
static constexpr int NCH = D / DC;   // 32

// smem float offsets (all strides 40 -> conflict-free LDS.64 fragment loads)
static constexpr int HS0 = 0;        // 128*40 = 5120
static constexpr int HS1 = 5120;
static constexpr int VB0 = 10240;    // 32*40 = 1280
static constexpr int VB1 = 11520;
static constexpr int PO  = 12800;    // P: 128*33 = 4224
static constexpr int WO  = 17024;    // W: 128*40 = 5120
static constexpr int SCO = 22144;    // C: 1024
static constexpr int SM_FLOATS = 23168;   // 92672 B -> 2 blocks/SM

__device__ float g_G[K * K];
__device__ float g_C[K * K];
__device__ float g_Vt[D * K];        // Vt[d][k]
__device__ int   g_cnt;

__device__ __forceinline__ void mma8(float* d, u32 a0, u32 a1, u32 a2, u32 a3,
                                     u32 b0, u32 b1) {
    asm volatile("mma.sync.aligned.m16n8k8.row.col.f32.tf32.tf32.f32 "
        "{%0,%1,%2,%3}, {%4,%5,%6,%7}, {%8,%9}, {%0,%1,%2,%3};"
        : "+f"(d[0]), "+f"(d[1]), "+f"(d[2]), "+f"(d[3])
        : "r"(a0), "r"(a1), "r"(a2), "r"(a3), "r"(b0), "r"(b1));
}
__device__ __forceinline__ void cp16(float* s, const float* g) {
    u32 ss = (u32)__cvta_generic_to_shared(s);
    asm volatile("cp.async.cg.shared.global [%0], [%1], 16;" :: "r"(ss), "l"(g) : "memory");
}
#define CP_COMMIT() asm volatile("cp.async.commit_group;" ::: "memory")
#define CP_WAIT1()  asm volatile("cp.async.wait_group 1;" ::: "memory")
#define CP_WAIT0()  asm volatile("cp.async.wait_group 0;" ::: "memory")
#define F2U(x) __float_as_uint(x)

// ---------------- prep: G = V V^T, g_Vt, then block 0 solves C ----------------
__global__ void prep_kernel(const float* __restrict__ V) {
    int k1 = blockIdx.x;
    int w = threadIdx.x >> 5;
    int lane = threadIdx.x & 31;
    #pragma unroll
    for (int i = 0; i < 4; i++) {
        int k2 = w * 4 + i;
        float s = 0.f;
        #pragma unroll
        for (int j = 0; j < D; j += 128) {
            float4 a = *(const float4*)(V + k1 * D + j + lane * 4);
            float4 b = *(const float4*)(V + k2 * D + j + lane * 4);
            s += a.x * b.x + a.y * b.y + a.z * b.z + a.w * b.w;
        }
        #pragma unroll
        for (int o = 16; o; o >>= 1) s += __shfl_down_sync(0xffffffffu, s, o);
        if (lane == 0) g_G[k1 * K + k2] = s;
    }
    for (int d = threadIdx.x; d < D; d += 256)
        g_Vt[d * K + k1] = V[k1 * D + d];

    __threadfence();
    __syncthreads();
    if (threadIdx.x == 0) atomicAdd(&g_cnt, 1);

    if (blockIdx.x == 0) {
        __shared__ float sG[K * K];
        __shared__ float sb[K];
        if (threadIdx.x == 0) {
            while (atomicAdd(&g_cnt, 0) < K) {}
            __threadfence();
        }
        __syncthreads();
        int t = threadIdx.x;
        for (int i = t; i < K * K; i += NT) sG[i] = g_G[i];
        __syncthreads();
        if (t < K) {
            sb[t] = 1.f / sG[t * K + t];
            __syncwarp();
            float x[K];
            int c = t;
            for (int j = 0; j < K; j++) x[j] = 0.f;
            x[c] = 1.f;
            for (int j = c - 1; j >= 0; j--) {   // (I+U) x = e_c
                float s = 0.f;
                for (int m = j + 1; m <= c; m++) s += sb[j] * sG[j * K + m] * x[m];
                x[j] = -s;
            }
            for (int j = 0; j < K; j++) g_C[j * K + c] = x[j] * sb[c];
        }
        __syncthreads();
        if (t == 0) atomicExch(&g_cnt, 0);   // reset for graph replay
    }
}

// ---------------- fused: out = h - ((h V^T) C) V, tf32 mma.sync ----------------
__global__ __launch_bounds__(NT) void fused_kernel(
    const float* __restrict__ H, const float* __restrict__ V,
    float* __restrict__ OUT)
{
    extern __shared__ __align__(16) float sm[];

    const int t = threadIdx.x;
    const int wid = t >> 5;
    const int lid = t & 31;
    const int g = lid >> 2;
    const int tq = lid & 3;
    const int w16 = wid * 16;
    const int row0 = blockIdx.x * TILE_R;

    float* sC = sm + SCO;
    for (int i = t; i < K * K; i += NT) sC[i] = g_C[i];

    const int fc = t & 7;
    const int sr = t >> 3;           // 0..31

    auto stageH = [&](int c, int b) {      // H tile 128x32, stride 40
        float* dst = sm + (b ? HS1 : HS0);
        int dc = c * DC;
        #pragma unroll
        for (int i = 0; i < 4; i++) {
            int seg = i * 256 + t, r = seg >> 3, c16 = seg & 7;
            cp16(dst + r * 40 + c16 * 4, H + (size_t)(row0 + r) * D + dc + c16 * 4);
        }
    };
    auto stageVs = [&](int c, int b) {     // V natural [k][d], stride 40 (phase A)
        float* dst = sm + (b ? VB1 : VB0);
        cp16(dst + sr * 40 + fc * 4, V + (size_t)sr * D + c * DC + fc * 4);
    };
    auto stageVt = [&](int c, int b) {     // Vt [d][k], stride 40 (phase B)
        float* dst = sm + (b ? VB1 : VB0);
        cp16(dst + sr * 40 + fc * 4, g_Vt + (size_t)(c * DC + sr) * K + fc * 4);
    };

    // ============ Phase A: P = H V^T (contraction over d, permuted) ============
    float pacc[4][4];
    #pragma unroll
    for (int nt = 0; nt < 4; nt++)
        #pragma unroll
        for (int i = 0; i < 4; i++) pacc[nt][i] = 0.f;

    stageH(0, 0); stageVs(0, 0); CP_COMMIT();
    for (int c = 0; c < NCH; c++) {
        int b = c & 1;
        if (c + 1 < NCH) {
            stageH(c + 1, b ^ 1); stageVs(c + 1, b ^ 1);
            CP_COMMIT(); CP_WAIT1();
        } else CP_WAIT0();
        __syncthreads();
        const float* hs = sm + (b ? HS1 : HS0);
        const float* vs = sm + (b ? VB1 : VB0);
        #pragma unroll
        for (int ks = 0; ks < 4; ks++) {
            int d0 = ks * 8 + 2 * tq;    // kk=tq -> d0, kk=tq+4 -> d0+1
            float2 av0 = *(const float2*)(&hs[(w16 + g) * 40 + d0]);
            float2 av1 = *(const float2*)(&hs[(w16 + g + 8) * 40 + d0]);
            #pragma unroll
            for (int nt = 0; nt < 4; nt++) {
                float2 bv = *(const float2*)(&vs[(nt * 8 + g) * 40 + d0]);
                mma8(pacc[nt], F2U(av0.x), F2U(av1.x), F2U(av0.y), F2U(av1.y),
                     F2U(bv.x), F2U(bv.y));
            }
        }
        __syncthreads();
    }

    // ---- P -> PO (stride 33) ----
    {
        float* P = sm + PO;
        #pragma unroll
        for (int nt = 0; nt < 4; nt++) {
            int cc = nt * 8 + 2 * tq;
            P[(w16 + g) * 33 + cc] = pacc[nt][0];
            P[(w16 + g) * 33 + cc + 1] = pacc[nt][1];
            P[(w16 + g + 8) * 33 + cc] = pacc[nt][2];
            P[(w16 + g + 8) * 33 + cc + 1] = pacc[nt][3];
        }
    }
    // prefetch phase-B chunk 0 (HS0/VB0 dead)
    stageH(0, 0); stageVt(0, 0); CP_COMMIT();
    __syncthreads();

    // ---- W = P C into WO (stride 40) ----
    {
        const float* P = sm + PO;
        float* W = sm + WO;
        int r = t & 127, half = t >> 7;
        float wv[16];
        #pragma unroll
        for (int i = 0; i < 16; i++) wv[i] = 0.f;
        #pragma unroll 4
        for (int j = 0; j < K; j++) {
            float pj = P[r * 33 + j];
            #pragma unroll
            for (int c4 = 0; c4 < 4; c4++) {
                float4 cv = *(const float4*)(&sC[j * K + half * 16 + c4 * 4]);
                wv[c4 * 4 + 0] += pj * cv.x;
                wv[c4 * 4 + 1] += pj * cv.y;
                wv[c4 * 4 + 2] += pj * cv.z;
                wv[c4 * 4 + 3] += pj * cv.w;
            }
        }
        #pragma unroll
        for (int i = 0; i < 16; i++) W[r * 40 + half * 16 + i] = wv[i];
    }
    __syncthreads();

    // hoist W a-fragments (permuted contraction: kk=tq -> k=k0+2tq, kk=tq+4 -> +1)
    u32 wa[4][4];
    {
        const float* W = sm + WO;
        #pragma unroll
        for (int ks = 0; ks < 4; ks++) {
            int k0 = ks * 8 + 2 * tq;
            float2 w0 = *(const float2*)(&W[(w16 + g) * 40 + k0]);
            float2 w1 = *(const float2*)(&W[(w16 + g + 8) * 40 + k0]);
            wa[ks][0] = F2U(w0.x); wa[ks][1] = F2U(w1.x);
            wa[ks][2] = F2U(w0.y); wa[ks][3] = F2U(w1.y);
        }
    }
    __syncthreads();

    // ============ Phase B: out = Hs - W V (epilogue straight from accumulators) ====
    for (int c = 0; c < NCH; c++) {
        int b = c & 1;
        if (c + 1 < NCH) {
            stageH(c + 1, b ^ 1); stageVt(c + 1, b ^ 1);
            CP_COMMIT(); CP_WAIT1();
        } else CP_WAIT0();
        __syncthreads();
        const float* hs = sm + (b ? HS1 : HS0);
        const float* vt = sm + (b ? VB1 : VB0);
        const int dc = c * DC;
        #pragma unroll
        for (int nt = 0; nt < 4; nt++) {
            float acc[4] = {0.f, 0.f, 0.f, 0.f};
            #pragma unroll
            for (int ks = 0; ks < 4; ks++) {
                int k0 = ks * 8 + 2 * tq;
                float2 bv = *(const float2*)(&vt[(nt * 8 + g) * 40 + k0]);
                mma8(acc, wa[ks][0], wa[ks][1], wa[ks][2], wa[ks][3],
                     F2U(bv.x), F2U(bv.y));
            }
            int cc = nt * 8 + 2 * tq;
            float2 h0 = *(const float2*)(&hs[(w16 + g) * 40 + cc]);
            float2 h1 = *(const float2*)(&hs[(w16 + g + 8) * 40 + cc]);
            float2 o0 = {h0.x - acc[0], h0.y - acc[1]};
            float2 o1 = {h1.x - acc[2], h1.y - acc[3]};
            *(float2*)(OUT + (size_t)(row0 + w16 + g) * D + dc + cc) = o0;
            *(float2*)(OUT + (size_t)(row0 + w16 + g + 8) * D + dc + cc) = o1;
        }
        __syncthreads();
    }
}

extern "C" void kernel_launch(void* const* d_in, const int* in_sizes, int n_in,
                              void* d_out, int out_size) {
    const float* H = (const float*)d_in[0];
    const float* V = (const float*)d_in[1];
    float* OUT = (float*)d_out;
    const int N = in_sizes[0] / D;

    cudaFuncSetAttribute(fused_kernel, cudaFuncAttributeMaxDynamicSharedMemorySize,
                         SM_FLOATS * 4);
    prep_kernel<<<K, NT>>>(V);
    fused_kernel<<<N / TILE_R, NT, SM_FLOATS * 4>>>(H, V, OUT);
}

// round 13
// speedup vs baseline: 1.5719x; 1.0085x over previous
#include <cuda_runtime.h>
#include <cstdint>

typedef unsigned int u32;

static constexpr int D = 1024;
static constexpr int K = 32;
static constexpr int NT = 256;       // 8 warps
static constexpr int TILE_R = 128;   // rows per block
static constexpr int DC = 32;        // d per chunk
static constexpr int NCH = D / DC;   // 32

// smem float offsets (stride 40 -> conflict-free LDS.64 fragment loads)
static constexpr int HS0 = 0;        // 128*40 = 5120
static constexpr int HS1 = 5120;
static constexpr int VB0 = 10240;    // 32*40 = 1280
static constexpr int VB1 = 11520;
static constexpr int PO  = 12800;    // P: 128*33 = 4224
static constexpr int SCO = 17024;    // C: 1024
static constexpr int SM_FLOATS = 18048;   // 72192 B -> 3 blocks/SM

__device__ float g_G[K * K];
__device__ float g_C[K * K];
__device__ float g_Vt[D * K];        // Vt[d][k]

__device__ __forceinline__ void mma8(float* d, u32 a0, u32 a1, u32 a2, u32 a3,
                                     u32 b0, u32 b1) {
    asm volatile("mma.sync.aligned.m16n8k8.row.col.f32.tf32.tf32.f32 "
        "{%0,%1,%2,%3}, {%4,%5,%6,%7}, {%8,%9}, {%0,%1,%2,%3};"
        : "+f"(d[0]), "+f"(d[1]), "+f"(d[2]), "+f"(d[3])
        : "r"(a0), "r"(a1), "r"(a2), "r"(a3), "r"(b0), "r"(b1));
}
__device__ __forceinline__ void cp16(float* s, const float* g) {
    u32 ss = (u32)__cvta_generic_to_shared(s);
    asm volatile("cp.async.cg.shared.global [%0], [%1], 16;" :: "r"(ss), "l"(g) : "memory");
}
#define CP_COMMIT() asm volatile("cp.async.commit_group;" ::: "memory")
#define CP_WAIT1()  asm volatile("cp.async.wait_group 1;" ::: "memory")
#define CP_WAIT0()  asm volatile("cp.async.wait_group 0;" ::: "memory")
#define F2U(x) __float_as_uint(x)

// ---------------- G = V V^T + build g_Vt ----------------
__global__ void gram_kernel(const float* __restrict__ V) {
    int k1 = blockIdx.x;
    int w = threadIdx.x >> 5;
    int lane = threadIdx.x & 31;
    #pragma unroll
    for (int i = 0; i < 4; i++) {
        int k2 = w * 4 + i;
        float s = 0.f;
        #pragma unroll
        for (int j = 0; j < D; j += 128) {
            float4 a = *(const float4*)(V + k1 * D + j + lane * 4);
            float4 b = *(const float4*)(V + k2 * D + j + lane * 4);
            s += a.x * b.x + a.y * b.y + a.z * b.z + a.w * b.w;
        }
        #pragma unroll
        for (int o = 16; o; o >>= 1) s += __shfl_down_sync(0xffffffffu, s, o);
        if (lane == 0) g_G[k1 * K + k2] = s;
    }
    for (int d = threadIdx.x; d < D; d += 256)
        g_Vt[d * K + k1] = V[k1 * D + d];
}

// ---------------- C = (I+U)^{-1} diag(beta) ----------------
__global__ void prepc_kernel() {
    __shared__ float G[K * K];
    __shared__ float beta[K];
    int t = threadIdx.x;
    for (int i = t; i < K * K; i += 32) G[i] = g_G[i];
    __syncwarp();
    beta[t] = 1.f / G[t * K + t];
    __syncwarp();
    float x[K];
    int c = t;
    for (int j = 0; j < K; j++) x[j] = 0.f;
    x[c] = 1.f;
    for (int j = c - 1; j >= 0; j--) {
        float s = 0.f;
        for (int m = j + 1; m <= c; m++) s += beta[j] * G[j * K + m] * x[m];
        x[j] = -s;
    }
    for (int j = 0; j < K; j++) g_C[j * K + c] = x[j] * beta[c];
}

// ---------------- fused: out = h - ((h V^T) C) V, tf32 mma.sync ----------------
__global__ __launch_bounds__(NT, 3) void fused_kernel(
    const float* __restrict__ H, const float* __restrict__ V,
    float* __restrict__ OUT)
{
    extern __shared__ __align__(16) float sm[];

    const int t = threadIdx.x;
    const int wid = t >> 5;
    const int lid = t & 31;
    const int g = lid >> 2;
    const int tq = lid & 3;
    const int w16 = wid * 16;
    const int row0 = blockIdx.x * TILE_R;

    float* sC = sm + SCO;
    for (int i = t; i < K * K; i += NT) sC[i] = g_C[i];

    const int fc = t & 7;
    const int sr = t >> 3;           // 0..31

    auto stageH = [&](int c, int b) {      // H tile 128x32, stride 40
        float* dst = sm + (b ? HS1 : HS0);
        int dc = c * DC;
        #pragma unroll
        for (int i = 0; i < 4; i++) {
            int seg = i * 256 + t, r = seg >> 3, c16 = seg & 7;
            cp16(dst + r * 40 + c16 * 4, H + (size_t)(row0 + r) * D + dc + c16 * 4);
        }
    };
    auto stageVs = [&](int c, int b) {     // V natural [k][d], stride 40 (phase A)
        float* dst = sm + (b ? VB1 : VB0);
        cp16(dst + sr * 40 + fc * 4, V + (size_t)sr * D + c * DC + fc * 4);
    };
    auto stageVt = [&](int c, int b) {     // Vt [d][k], stride 40 (phase B)
        float* dst = sm + (b ? VB1 : VB0);
        cp16(dst + sr * 40 + fc * 4, g_Vt + (size_t)(c * DC + sr) * K + fc * 4);
    };

    // ============ Phase A: P = H V^T (contraction over d, permuted) ============
    float pacc[4][4];
    #pragma unroll
    for (int nt = 0; nt < 4; nt++)
        #pragma unroll
        for (int i = 0; i < 4; i++) pacc[nt][i] = 0.f;

    stageH(0, 0); stageVs(0, 0); CP_COMMIT();
    for (int c = 0; c < NCH; c++) {
        int b = c & 1;
        if (c + 1 < NCH) {
            stageH(c + 1, b ^ 1); stageVs(c + 1, b ^ 1);
            CP_COMMIT(); CP_WAIT1();
        } else CP_WAIT0();
        __syncthreads();
        const float* hs = sm + (b ? HS1 : HS0);
        const float* vs = sm + (b ? VB1 : VB0);
        #pragma unroll
        for (int ks = 0; ks < 4; ks++) {
            int d0 = ks * 8 + 2 * tq;    // kk=tq -> d0, kk=tq+4 -> d0+1
            float2 av0 = *(const float2*)(&hs[(w16 + g) * 40 + d0]);
            float2 av1 = *(const float2*)(&hs[(w16 + g + 8) * 40 + d0]);
            #pragma unroll
            for (int nt = 0; nt < 4; nt++) {
                float2 bv = *(const float2*)(&vs[(nt * 8 + g) * 40 + d0]);
                mma8(pacc[nt], F2U(av0.x), F2U(av1.x), F2U(av0.y), F2U(av1.y),
                     F2U(bv.x), F2U(bv.y));
            }
        }
        __syncthreads();
    }

    // ---- P -> PO (stride 33) ----
    {
        float* P = sm + PO;
        #pragma unroll
        for (int nt = 0; nt < 4; nt++) {
            int cc = nt * 8 + 2 * tq;
            P[(w16 + g) * 33 + cc] = pacc[nt][0];
            P[(w16 + g) * 33 + cc + 1] = pacc[nt][1];
            P[(w16 + g + 8) * 33 + cc] = pacc[nt][2];
            P[(w16 + g + 8) * 33 + cc + 1] = pacc[nt][3];
        }
    }
    __syncthreads();

    // prefetch phase-B chunk 0 (HS0/VB0 dead after last A chunk used buf 1)
    stageH(0, 0); stageVt(0, 0); CP_COMMIT();

    // ---- W fragments per-thread: wa[ks] = {W[r0][k0], W[r1][k0], W[r0][k0+1], W[r1][k0+1]}
    //      where r0=w16+g, r1=w16+g+8, k0=ks*8+2tq;  W[r][k] = sum_j P[r][j] C[j][k]
    u32 wa[4][4];
    {
        const float* P = sm + PO;
        float w0[8], w1[8];              // [ks*2 + {0,1}]
        #pragma unroll
        for (int i = 0; i < 8; i++) { w0[i] = 0.f; w1[i] = 0.f; }
        #pragma unroll 4
        for (int j = 0; j < K; j++) {
            float p0 = P[(w16 + g) * 33 + j];
            float p1 = P[(w16 + g + 8) * 33 + j];
            #pragma unroll
            for (int ks = 0; ks < 4; ks++) {
                float2 cv = *(const float2*)(&sC[j * K + ks * 8 + 2 * tq]);
                w0[ks * 2 + 0] += p0 * cv.x;
                w0[ks * 2 + 1] += p0 * cv.y;
                w1[ks * 2 + 0] += p1 * cv.x;
                w1[ks * 2 + 1] += p1 * cv.y;
            }
        }
        #pragma unroll
        for (int ks = 0; ks < 4; ks++) {
            wa[ks][0] = F2U(w0[ks * 2 + 0]);
            wa[ks][1] = F2U(w1[ks * 2 + 0]);
            wa[ks][2] = F2U(w0[ks * 2 + 1]);
            wa[ks][3] = F2U(w1[ks * 2 + 1]);
        }
    }

    // ============ Phase B: out = Hs - W V (epilogue straight from accumulators) ====
    for (int c = 0; c < NCH; c++) {
        int b = c & 1;
        if (c + 1 < NCH) {
            stageH(c + 1, b ^ 1); stageVt(c + 1, b ^ 1);
            CP_COMMIT(); CP_WAIT1();
        } else CP_WAIT0();
        __syncthreads();
        const float* hs = sm + (b ? HS1 : HS0);
        const float* vt = sm + (b ? VB1 : VB0);
        const int dc = c * DC;
        #pragma unroll
        for (int nt = 0; nt < 4; nt++) {
            float acc[4] = {0.f, 0.f, 0.f, 0.f};
            #pragma unroll
            for (int ks = 0; ks < 4; ks++) {
                int k0 = ks * 8 + 2 * tq;
                float2 bv = *(const float2*)(&vt[(nt * 8 + g) * 40 + k0]);
                mma8(acc, wa[ks][0], wa[ks][1], wa[ks][2], wa[ks][3],
                     F2U(bv.x), F2U(bv.y));
            }
            int cc = nt * 8 + 2 * tq;
            float2 h0 = *(const float2*)(&hs[(w16 + g) * 40 + cc]);
            float2 h1 = *(const float2*)(&hs[(w16 + g + 8) * 40 + cc]);
            float2 o0 = {h0.x - acc[0], h0.y - acc[1]};
            float2 o1 = {h1.x - acc[2], h1.y - acc[3]};
            *(float2*)(OUT + (size_t)(row0 + w16 + g) * D + dc + cc) = o0;
            *(float2*)(OUT + (size_t)(row0 + w16 + g + 8) * D + dc + cc) = o1;
        }
        __syncthreads();
    }
}

extern "C" void kernel_launch(void* const* d_in, const int* in_sizes, int n_in,
                              void* d_out, int out_size) {
    const float* H = (const float*)d_in[0];
    const float* V = (const float*)d_in[1];
    float* OUT = (float*)d_out;
    const int N = in_sizes[0] / D;

    cudaFuncSetAttribute(fused_kernel, cudaFuncAttributeMaxDynamicSharedMemorySize,
                         SM_FLOATS * 4);
    gram_kernel<<<K, 256>>>(V);
    prepc_kernel<<<1, 32>>>();
    fused_kernel<<<N / TILE_R, NT, SM_FLOATS * 4>>>(H, V, OUT);
}